// round 12
// baseline (speedup 1.0000x reference)
#include <cuda_runtime.h>
#include <cuda_fp16.h>
#include <stdint.h>
#include <math.h>

#define B_   256
#define T_   500
#define M_   512
#define L_   128
#define NROWS (B_ * T_)    // 128000

// ---- phase-1 tiling ----
#define MT   128            // rows / CTA
#define NN   256            // cols (V:0..127, U:128..255)
#define KC   64             // fp32 k per stage -> 128B fp16 rows (SW128)
#define NST  (M_ / KC)      // 8 stages
#define NTH  256            // 8 warps; warp tile 64x64 (2 rw x 4 cw)

// smem stage: {A 16K, B 32K} = 48KB; two stages + Wc 4K
#define BUF     49152
#define SMEM_P1 (2 * BUF + 4096)   // 102400

// W (fp16), [n][k] row-major, 16B aligned
__device__ __align__(16) unsigned short g_Whi[NN * M_];
// fused per-row projection dots: G[b*T+t][k] = H[b,t,:]. Wc[k,:]
__device__ float g_G[NROWS * 2];

// ===================== helpers =====================
__device__ __forceinline__ uint32_t smem_u32(const void* p) {
    uint32_t a;
    asm("{ .reg .u64 t; cvta.to.shared.u64 t, %1; cvt.u32.u64 %0, t; }"
        : "=r"(a) : "l"(p));
    return a;
}
__device__ __forceinline__ uint32_t swz(uint32_t o) { return o ^ ((o >> 3) & 0x70); }

__device__ __forceinline__ void ldsm4(uint32_t a, uint32_t& r0, uint32_t& r1,
                                      uint32_t& r2, uint32_t& r3) {
    asm volatile("ldmatrix.sync.aligned.m8n8.x4.shared.b16 {%0,%1,%2,%3}, [%4];"
                 : "=r"(r0), "=r"(r1), "=r"(r2), "=r"(r3) : "r"(a));
}
__device__ __forceinline__ void mma16816(float* c, uint32_t a0, uint32_t a1,
                                         uint32_t a2, uint32_t a3,
                                         uint32_t b0, uint32_t b1) {
    asm volatile(
        "mma.sync.aligned.m16n8k16.row.col.f32.f16.f16.f32 "
        "{%0,%1,%2,%3}, {%4,%5,%6,%7}, {%8,%9}, {%0,%1,%2,%3};"
        : "+f"(c[0]), "+f"(c[1]), "+f"(c[2]), "+f"(c[3])
        : "r"(a0), "r"(a1), "r"(a2), "r"(a3), "r"(b0), "r"(b1));
}
#define CP16(dst, src) \
    asm volatile("cp.async.cg.shared.global [%0], [%1], 16;" :: "r"(dst), "l"(src))
#define CP_COMMIT() asm volatile("cp.async.commit_group;" ::: "memory")
#define CP_WAIT0()  asm volatile("cp.async.wait_group 0;" ::: "memory")
#define STS128(a, x, y, z, w) \
    asm volatile("st.shared.v4.b32 [%0], {%1,%2,%3,%4};" \
                 :: "r"(a), "r"(x), "r"(y), "r"(z), "r"(w))

__device__ __forceinline__ uint32_t h2_u32(float a, float b) {
    __half2 h = __floats2half2_rn(a, b);
    return *reinterpret_cast<uint32_t*>(&h);
}
__device__ __forceinline__ float tanh_fast(float x) {
    float y;
    asm("tanh.approx.f32 %0, %1;" : "=f"(y) : "f"(x));
    return y;
}

// ---------------------------------------------------------------------------
// Convert W = [Wv;Wu] to fp16 (once per launch; 256KB)
// ---------------------------------------------------------------------------
__global__ void wsplit_kernel(const float* __restrict__ Wv, const float* __restrict__ Wu)
{
    int idx = blockIdx.x * 256 + threadIdx.x;          // 0 .. 131071
    int n = idx >> 9, k = idx & 511;
    float x = (n < L_) ? Wv[n * M_ + k] : Wu[(n - L_) * M_ + k];
    __half h = __float2half_rn(x);
    g_Whi[idx] = *reinterpret_cast<unsigned short*>(&h);
}

// ---------------------------------------------------------------------------
// Phase 1: fp16 mma.sync GEMM (64x64 warp tiles) + fused activation -> A_pre
//          + fused per-row Wc projection dots -> g_G
// ---------------------------------------------------------------------------
__device__ __forceinline__ void load_B_async(uint32_t bufb, int kt, int tid)
{
    const unsigned short* sh = g_Whi + tid * M_ + kt * KC;
    const uint32_t dh = bufb + 16384;
#pragma unroll
    for (int j = 0; j < 8; ++j) {
        uint32_t off = swz((uint32_t)(tid * 128 + j * 16));
        CP16(dh + off, sh + j * 8);
    }
}

// store A tile as fp16 (32 floats/thread)
__device__ __forceinline__ void sts_A(uint32_t bufb, const float4* f, int tid)
{
    const int row = tid >> 1, half = tid & 1;
    const uint32_t base = (uint32_t)(row * 128 + half * 64);
#pragma unroll
    for (int j = 0; j < 4; ++j) {
        uint32_t w0 = h2_u32(f[2 * j].x, f[2 * j].y);
        uint32_t w1 = h2_u32(f[2 * j].z, f[2 * j].w);
        uint32_t w2 = h2_u32(f[2 * j + 1].x, f[2 * j + 1].y);
        uint32_t w3 = h2_u32(f[2 * j + 1].z, f[2 * j + 1].w);
        STS128(bufb + swz(base + j * 16), w0, w1, w2, w3);
    }
}

// accumulate G partial dots from an fp32 A fragment (32 k values)
__device__ __forceinline__ void acc_G(const float* WcS, const float4* f, int kbase,
                                      float& pd0, float& pd1)
{
#pragma unroll
    for (int i = 0; i < 8; ++i) {
        float4 w0 = *reinterpret_cast<const float4*>(WcS + kbase + i * 4);
        float4 w1 = *reinterpret_cast<const float4*>(WcS + 512 + kbase + i * 4);
        pd0 += f[i].x * w0.x + f[i].y * w0.y + f[i].z * w0.z + f[i].w * w0.w;
        pd1 += f[i].x * w1.x + f[i].y * w1.y + f[i].z * w1.z + f[i].w * w1.w;
    }
}

#define UPAD 133   // floats per Uact row (conflict-free)

__global__ __launch_bounds__(NTH, 1)
void mil_phase1_mma(const float* __restrict__ H,
                    const float* __restrict__ bv, const float* __restrict__ bu,
                    const float* __restrict__ Ww, const float* __restrict__ bw,
                    const float* __restrict__ Wc,
                    float* __restrict__ A_pre)
{
    extern __shared__ __align__(1024) char smem[];
    const uint32_t sb = smem_u32(smem);
    const int tid  = threadIdx.x;
    const int lane = tid & 31;
    const int warp = tid >> 5;
    const int rw   = warp >> 2;      // 0..1 row group (64 rows)
    const int cw   = warp & 3;       // 0..3 col group (64 cols)
    const int row0 = blockIdx.x * MT;

    float* WcS = reinterpret_cast<float*>(smem + 2 * BUF);   // [2][512]
#pragma unroll
    for (int i = 0; i < 4; ++i)
        WcS[tid + i * 256] = Wc[tid + i * 256];

    float acc[4][4][2][4];
#pragma unroll
    for (int a = 0; a < 4; ++a)
#pragma unroll
        for (int b = 0; b < 4; ++b)
#pragma unroll
            for (int c = 0; c < 2; ++c)
#pragma unroll
                for (int d = 0; d < 4; ++d) acc[a][b][c][d] = 0.f;

    const float* gA = H + (size_t)(row0 + (tid >> 1)) * M_ + (tid & 1) * 32;
    const int kb0 = (tid & 1) * 32;       // k base of this thread's fragment
    float pd0 = 0.f, pd1 = 0.f;           // G partial dots

    // ldmatrix per-lane address components
    const int lrow = lane & 15;
    const int lko  = (lane >> 4) * 16;
    int arow[4];
#pragma unroll
    for (int mt = 0; mt < 4; ++mt)
        arow[mt] = (rw * 64 + mt * 16 + lrow) * 128;

    // ---- prologue: stage 0 ----
    load_B_async(sb, 0, tid);
    CP_COMMIT();
    float4 f0[8];
#pragma unroll
    for (int i = 0; i < 8; ++i)
        f0[i] = *reinterpret_cast<const float4*>(gA + i * 4);
    sts_A(sb, f0, tid);
    CP_WAIT0();
    __syncthreads();            // also publishes WcS
    acc_G(WcS, f0, kb0, pd0, pd1);

    // ---- main loop ----
    for (int kt = 0; kt < NST; ++kt) {
        const uint32_t bufc = sb + (uint32_t)(kt & 1) * BUF;
        const uint32_t bufn = sb + (uint32_t)((kt + 1) & 1) * BUF;

        float4 fA[8];
        if (kt < NST - 1) {
            const float* s = gA + (kt + 1) * KC;
#pragma unroll
            for (int i = 0; i < 8; ++i)
                fA[i] = *reinterpret_cast<const float4*>(s + i * 4);
            load_B_async(bufn, kt + 1, tid);
            CP_COMMIT();
        }

        // compute stage kt: 4 k16-steps, 32 HMMA each
#pragma unroll
        for (int ks = 0; ks < 4; ++ks) {
            const uint32_t kb = (uint32_t)(ks * 32 + lko);
            uint32_t ah[4][4];
#pragma unroll
            for (int mt = 0; mt < 4; ++mt)
                ldsm4(bufc + swz((uint32_t)arow[mt] + kb),
                      ah[mt][0], ah[mt][1], ah[mt][2], ah[mt][3]);
#pragma unroll
            for (int ng = 0; ng < 4; ++ng) {
                const uint32_t bro = (uint32_t)((cw * 64 + ng * 16 + lrow) * 128) + kb;
                uint32_t bh0, bh1, bh2, bh3;
                ldsm4(bufc + 16384 + swz(bro), bh0, bh1, bh2, bh3);
#pragma unroll
                for (int mt = 0; mt < 4; ++mt) {
                    mma16816(acc[mt][ng][0], ah[mt][0], ah[mt][1], ah[mt][2], ah[mt][3], bh0, bh2);
                    mma16816(acc[mt][ng][1], ah[mt][0], ah[mt][1], ah[mt][2], ah[mt][3], bh1, bh3);
                }
            }
        }

        if (kt < NST - 1) {
            acc_G(WcS, fA, kb0 + (kt + 1) * KC, pd0, pd1);
            sts_A(bufn, fA, tid);
            CP_WAIT0();
        }
        __syncthreads();
    }

    // ---- G write: reduce pd over the 2 threads sharing a row ----
    pd0 += __shfl_xor_sync(0xffffffffu, pd0, 1);
    pd1 += __shfl_xor_sync(0xffffffffu, pd1, 1);
    if ((tid & 1) == 0) {
        const size_t gr = (size_t)(row0 + (tid >> 1)) * 2;
        g_G[gr]     = pd0;
        g_G[gr + 1] = pd1;
    }

    // ---- epilogue ----
    float* Uact = reinterpret_cast<float*>(smem);              // [128][UPAD]
    float* part = reinterpret_cast<float*>(smem) + 128 * UPAD; // [2][128]

    if (cw >= 2) {   // U half: sigma(U + bu) -> Uact
#pragma unroll
        for (int mt = 0; mt < 4; ++mt)
#pragma unroll
            for (int ng = 0; ng < 4; ++ng)
#pragma unroll
                for (int h = 0; h < 2; ++h)
#pragma unroll
                    for (int e = 0; e < 4; ++e) {
                        int r  = rw * 64 + mt * 16 + (lane >> 2) + (e >= 2 ? 8 : 0);
                        int uc = (cw - 2) * 64 + ng * 16 + h * 8 + (lane & 3) * 2 + (e & 1);
                        float x = acc[mt][ng][h][e] + __ldg(&bu[uc]);
                        Uact[r * UPAD + uc] = 1.f / (1.f + __expf(-x));
                    }
    }
    __syncthreads();

    if (cw < 2) {    // V half: tanh(V + bv)*Ww * Uact, row-reduce
        float srow[4][2];
#pragma unroll
        for (int mt = 0; mt < 4; ++mt) { srow[mt][0] = 0.f; srow[mt][1] = 0.f; }
#pragma unroll
        for (int mt = 0; mt < 4; ++mt)
#pragma unroll
            for (int ng = 0; ng < 4; ++ng)
#pragma unroll
                for (int h = 0; h < 2; ++h)
#pragma unroll
                    for (int e = 0; e < 4; ++e) {
                        int rh = (e >= 2) ? 1 : 0;
                        int r  = rw * 64 + mt * 16 + (lane >> 2) + rh * 8;
                        int c  = cw * 64 + ng * 16 + h * 8 + (lane & 3) * 2 + (e & 1);
                        float x = acc[mt][ng][h][e] + __ldg(&bv[c]);
                        float v = tanh_fast(x) * __ldg(&Ww[c]);
                        srow[mt][rh] += v * Uact[r * UPAD + c];
                    }
#pragma unroll
        for (int mt = 0; mt < 4; ++mt)
#pragma unroll
            for (int rh = 0; rh < 2; ++rh) {
                srow[mt][rh] += __shfl_xor_sync(0xffffffffu, srow[mt][rh], 1);
                srow[mt][rh] += __shfl_xor_sync(0xffffffffu, srow[mt][rh], 2);
            }
        if ((lane & 3) == 0) {
#pragma unroll
            for (int mt = 0; mt < 4; ++mt)
#pragma unroll
                for (int rh = 0; rh < 2; ++rh) {
                    int r = rw * 64 + mt * 16 + (lane >> 2) + rh * 8;
                    part[cw * 128 + r] = srow[mt][rh];
                }
        }
    }
    __syncthreads();

    if (tid < MT)
        A_pre[(size_t)(row0 + tid)] = part[tid] + part[128 + tid] + bw[0];
}

// ---------------------------------------------------------------------------
// Phase 2+3 merged: per-bag softmax -> A_sftmx, then
// out[b,k] = sum_t a[t]*G[b,t,k] + bc[k]*bias_rel
// ---------------------------------------------------------------------------
__global__ __launch_bounds__(256)
void mil_finish(const float* __restrict__ A_pre,
                const float* __restrict__ bc,
                float* __restrict__ Asm, float* __restrict__ out)
{
    __shared__ float sh0[256];
    __shared__ float sh1[256];
    __shared__ float sh2[256];
    const int b   = blockIdx.x;
    const int tid = threadIdx.x;
    const float* src = A_pre + (size_t)b * T_;

    const int t0 = tid, t1 = tid + 256;
    float v0 = src[t0];
    float v1 = (t1 < T_) ? src[t1] : -INFINITY;

    sh0[tid] = fmaxf(v0, v1);
    __syncthreads();
    for (int s = 128; s > 0; s >>= 1) {
        if (tid < s) sh0[tid] = fmaxf(sh0[tid], sh0[tid + s]);
        __syncthreads();
    }
    const float mx = sh0[0];
    __syncthreads();

    float e0 = expf(v0 - mx);
    float e1 = (t1 < T_) ? expf(v1 - mx) : 0.f;
    sh0[tid] = e0 + e1;
    __syncthreads();
    for (int s = 128; s > 0; s >>= 1) {
        if (tid < s) sh0[tid] += sh0[tid + s];
        __syncthreads();
    }
    const float inv = 1.f / sh0[0];
    __syncthreads();

    const float a0 = e0 * inv;
    const float a1 = e1 * inv;
    Asm[(size_t)b * T_ + t0] = a0;
    if (t1 < T_) Asm[(size_t)b * T_ + t1] = a1;

    const float* Gb = g_G + (size_t)b * T_ * 2;
    float c0 = a0 * Gb[t0 * 2]     + ((t1 < T_) ? a1 * Gb[t1 * 2]     : 0.f);
    float c1 = a0 * Gb[t0 * 2 + 1] + ((t1 < T_) ? a1 * Gb[t1 * 2 + 1] : 0.f);

    sh0[tid] = a0 + a1;   // bias_rel partial
    sh1[tid] = c0;
    sh2[tid] = c1;
    __syncthreads();
    for (int s = 128; s > 0; s >>= 1) {
        if (tid < s) {
            sh0[tid] += sh0[tid + s];
            sh1[tid] += sh1[tid + s];
            sh2[tid] += sh2[tid + s];
        }
        __syncthreads();
    }
    if (tid == 0) {
        const float bias_rel = sh0[0];
        out[(size_t)b * 2 + 0] = sh1[0] + bc[0] * bias_rel;
        out[(size_t)b * 2 + 1] = sh2[0] + bc[1] * bias_rel;
    }
}

// ---------------------------------------------------------------------------
// Launch: d_out = (out[256,2], A_sftmx[256,500], A_pre[256,1,500])
// ---------------------------------------------------------------------------
extern "C" void kernel_launch(void* const* d_in, const int* in_sizes, int n_in,
                              void* d_out, int out_size)
{
    const float* H  = (const float*)d_in[0];
    const float* Wv = (const float*)d_in[1];
    const float* bv = (const float*)d_in[2];
    const float* Wu = (const float*)d_in[3];
    const float* bu = (const float*)d_in[4];
    const float* Ww = (const float*)d_in[5];
    const float* bw = (const float*)d_in[6];
    const float* Wc = (const float*)d_in[7];
    const float* bc = (const float*)d_in[8];

    float* out   = (float*)d_out;               // [256,2]
    float* A_sm  = out + (size_t)B_ * 2;        // [256,500]
    float* A_pre = A_sm + (size_t)B_ * T_;      // [256,1,500]

    // one-time, non-stream host config (no-op during graph capture replays)
    static bool configured = false;
    if (!configured) {
        cudaFuncSetAttribute(mil_phase1_mma,
                             cudaFuncAttributeMaxDynamicSharedMemorySize, SMEM_P1);
        configured = true;
    }

    wsplit_kernel<<<(NN * M_) / 256, 256>>>(Wv, Wu);
    mil_phase1_mma<<<NROWS / MT, NTH, SMEM_P1>>>(H, bv, bu, Ww, bw, Wc, A_pre);
    mil_finish<<<B_, 256>>>(A_pre, bc, A_sm, out);
}

// round 13
// speedup vs baseline: 1.5117x; 1.5117x over previous
#include <cuda_runtime.h>
#include <cuda_fp16.h>
#include <stdint.h>
#include <math.h>

#define B_   256
#define T_   500
#define M_   512
#define L_   128
#define NROWS (B_ * T_)    // 128000

// ---- phase-1 tiling (R10 geometry) ----
#define MT   128            // rows / CTA
#define NN   256            // cols, PERMUTED: warp g owns {V[g*32..+32], U[g*32..+32]}
#define KC   64             // fp32 k per stage -> 128B fp16 rows (SW128)
#define NST  (M_ / KC)      // 8 stages
#define NTH  512            // 16 warps; warp tile 32x64; 2 CTAs/SM

// smem stage: {A 16K, B 32K} = 48KB; two stages + Wc 4K
#define BUF     49152
#define SMEM_P1 (2 * BUF + 4096)   // 102400

// W (fp16), permuted rows (see wsplit), [n][k] row-major, 16B aligned
__device__ __align__(16) unsigned short g_Whi[NN * M_];
// fused per-row projection dots: G[b*T+t][k] = H[b,t,:]. Wc[k,:]
__device__ float g_G[NROWS * 2];

// ===================== helpers =====================
__device__ __forceinline__ uint32_t smem_u32(const void* p) {
    uint32_t a;
    asm("{ .reg .u64 t; cvta.to.shared.u64 t, %1; cvt.u32.u64 %0, t; }"
        : "=r"(a) : "l"(p));
    return a;
}
__device__ __forceinline__ uint32_t swz(uint32_t o) { return o ^ ((o >> 3) & 0x70); }

__device__ __forceinline__ void ldsm4(uint32_t a, uint32_t& r0, uint32_t& r1,
                                      uint32_t& r2, uint32_t& r3) {
    asm volatile("ldmatrix.sync.aligned.m8n8.x4.shared.b16 {%0,%1,%2,%3}, [%4];"
                 : "=r"(r0), "=r"(r1), "=r"(r2), "=r"(r3) : "r"(a));
}
__device__ __forceinline__ void mma16816(float* c, uint32_t a0, uint32_t a1,
                                         uint32_t a2, uint32_t a3,
                                         uint32_t b0, uint32_t b1) {
    asm volatile(
        "mma.sync.aligned.m16n8k16.row.col.f32.f16.f16.f32 "
        "{%0,%1,%2,%3}, {%4,%5,%6,%7}, {%8,%9}, {%0,%1,%2,%3};"
        : "+f"(c[0]), "+f"(c[1]), "+f"(c[2]), "+f"(c[3])
        : "r"(a0), "r"(a1), "r"(a2), "r"(a3), "r"(b0), "r"(b1));
}
#define CP16(dst, src) \
    asm volatile("cp.async.cg.shared.global [%0], [%1], 16;" :: "r"(dst), "l"(src))
#define CP_COMMIT() asm volatile("cp.async.commit_group;" ::: "memory")
#define CP_WAIT0()  asm volatile("cp.async.wait_group 0;" ::: "memory")
#define STS128(a, x, y, z, w) \
    asm volatile("st.shared.v4.b32 [%0], {%1,%2,%3,%4};" \
                 :: "r"(a), "r"(x), "r"(y), "r"(z), "r"(w))

__device__ __forceinline__ uint32_t h2_u32(float a, float b) {
    __half2 h = __floats2half2_rn(a, b);
    return *reinterpret_cast<uint32_t*>(&h);
}
__device__ __forceinline__ float tanh_fast(float x) {
    float y;
    asm("tanh.approx.f32 %0, %1;" : "=f"(y) : "f"(x));
    return y;
}

// ---------------------------------------------------------------------------
// Convert W to fp16 with PERMUTED row order (once per launch; 256KB).
// GEMM row n: g = n>>6, r = n&63; l = g*32 + (r&31);
//   r < 32  -> Wv[l]   (V half of warp g's tile)
//   r >= 32 -> Wu[l]   (U half, same l range -> register pairing in epilogue)
// ---------------------------------------------------------------------------
__global__ void wsplit_kernel(const float* __restrict__ Wv, const float* __restrict__ Wu)
{
    int idx = blockIdx.x * 256 + threadIdx.x;          // 0 .. 131071
    int n = idx >> 9, k = idx & 511;
    int g = n >> 6, r = n & 63;
    int l = g * 32 + (r & 31);
    float x = (r < 32) ? Wv[l * M_ + k] : Wu[l * M_ + k];
    __half h = __float2half_rn(x);
    g_Whi[idx] = *reinterpret_cast<unsigned short*>(&h);
}

// ---------------------------------------------------------------------------
// Phase 1: fp16 mma.sync GEMM (R10 geometry) + register-paired epilogue
//          + fused per-row Wc projection dots -> g_G
// ---------------------------------------------------------------------------
__device__ __forceinline__ void load_B_async(uint32_t bufb, int kt, int tid)
{
    const int row = tid >> 1, half = tid & 1;
    const unsigned short* sh = g_Whi + row * M_ + kt * KC + half * 32;
    const uint32_t dh = bufb + 16384;
#pragma unroll
    for (int j = 0; j < 4; ++j) {
        uint32_t off = swz((uint32_t)(row * 128 + (half * 4 + j) * 16));
        CP16(dh + off, sh + j * 8);
    }
}

// store A tile as fp16 (16 floats/thread)
__device__ __forceinline__ void sts_A(uint32_t bufb, const float4* f, int tid)
{
    const int row = tid >> 2, q = tid & 3;
    uint32_t w0 = h2_u32(f[0].x, f[0].y);
    uint32_t w1 = h2_u32(f[0].z, f[0].w);
    uint32_t w2 = h2_u32(f[1].x, f[1].y);
    uint32_t w3 = h2_u32(f[1].z, f[1].w);
    STS128(bufb + swz((uint32_t)(row * 128 + q * 32)), w0, w1, w2, w3);
    w0 = h2_u32(f[2].x, f[2].y);
    w1 = h2_u32(f[2].z, f[2].w);
    w2 = h2_u32(f[3].x, f[3].y);
    w3 = h2_u32(f[3].z, f[3].w);
    STS128(bufb + swz((uint32_t)(row * 128 + q * 32 + 16)), w0, w1, w2, w3);
}

// accumulate G partial dots from an fp32 A fragment (16 k values)
__device__ __forceinline__ void acc_G(const float* WcS, const float4* f, int kbase,
                                      float& pd0, float& pd1)
{
#pragma unroll
    for (int i = 0; i < 4; ++i) {
        float4 w0 = *reinterpret_cast<const float4*>(WcS + kbase + i * 4);
        float4 w1 = *reinterpret_cast<const float4*>(WcS + 512 + kbase + i * 4);
        pd0 += f[i].x * w0.x + f[i].y * w0.y + f[i].z * w0.z + f[i].w * w0.w;
        pd1 += f[i].x * w1.x + f[i].y * w1.y + f[i].z * w1.z + f[i].w * w1.w;
    }
}

__global__ __launch_bounds__(NTH, 1)
void mil_phase1_mma(const float* __restrict__ H,
                    const float* __restrict__ bv, const float* __restrict__ bu,
                    const float* __restrict__ Ww, const float* __restrict__ bw,
                    const float* __restrict__ Wc,
                    float* __restrict__ A_pre)
{
    extern __shared__ __align__(1024) char smem[];
    const uint32_t sb = smem_u32(smem);
    const int tid  = threadIdx.x;
    const int lane = tid & 31;
    const int warp = tid >> 5;
    const int rw   = warp >> 2;      // 0..3 row group (32 rows)
    const int cw   = warp & 3;       // 0..3 col group (64 permuted cols = 32 l)
    const int row0 = blockIdx.x * MT;

    float* WcS = reinterpret_cast<float*>(smem + 2 * BUF);   // [2][512]
    WcS[tid]       = Wc[tid];
    WcS[tid + 512] = Wc[tid + 512];

    float acc[2][4][2][4];
#pragma unroll
    for (int a = 0; a < 2; ++a)
#pragma unroll
        for (int b = 0; b < 4; ++b)
#pragma unroll
            for (int c = 0; c < 2; ++c)
#pragma unroll
                for (int d = 0; d < 4; ++d) acc[a][b][c][d] = 0.f;

    const float* gA = H + (size_t)(row0 + (tid >> 2)) * M_ + (tid & 3) * 16;
    const int kb0 = (tid & 3) * 16;       // k base of this thread's fragment
    float pd0 = 0.f, pd1 = 0.f;           // G partial dots

    // ldmatrix per-lane address components
    const int lrow = lane & 15;
    const int lko  = (lane >> 4) * 16;
    const int arow0 = (rw * 32 + lrow) * 128;          // mt=0
    const int arow1 = (rw * 32 + 16 + lrow) * 128;     // mt=1

    // ---- prologue: stage 0 ----
    load_B_async(sb, 0, tid);
    CP_COMMIT();
    float4 f0[4];
#pragma unroll
    for (int i = 0; i < 4; ++i)
        f0[i] = *reinterpret_cast<const float4*>(gA + i * 4);
    sts_A(sb, f0, tid);
    CP_WAIT0();
    __syncthreads();            // also publishes WcS
    acc_G(WcS, f0, kb0, pd0, pd1);

    // ---- main loop ----
    for (int kt = 0; kt < NST; ++kt) {
        const uint32_t bufc = sb + (uint32_t)(kt & 1) * BUF;
        const uint32_t bufn = sb + (uint32_t)((kt + 1) & 1) * BUF;

        float4 fA[4];
        if (kt < NST - 1) {
            const float* s = gA + (kt + 1) * KC;
#pragma unroll
            for (int i = 0; i < 4; ++i)
                fA[i] = *reinterpret_cast<const float4*>(s + i * 4);
            load_B_async(bufn, kt + 1, tid);
            CP_COMMIT();
        }

        // compute stage kt: 4 k16-steps
#pragma unroll
        for (int ks = 0; ks < 4; ++ks) {
            const uint32_t kb = (uint32_t)(ks * 32 + lko);
            uint32_t ah[2][4];
            ldsm4(bufc + swz(arow0 + kb), ah[0][0], ah[0][1], ah[0][2], ah[0][3]);
            ldsm4(bufc + swz(arow1 + kb), ah[1][0], ah[1][1], ah[1][2], ah[1][3]);
#pragma unroll
            for (int ng = 0; ng < 4; ++ng) {
                const uint32_t bro = (uint32_t)((cw * 64 + ng * 16 + lrow) * 128) + kb;
                uint32_t bh0, bh1, bh2, bh3;
                ldsm4(bufc + 16384 + swz(bro), bh0, bh1, bh2, bh3);
#pragma unroll
                for (int mt = 0; mt < 2; ++mt) {
                    mma16816(acc[mt][ng][0], ah[mt][0], ah[mt][1], ah[mt][2], ah[mt][3], bh0, bh2);
                    mma16816(acc[mt][ng][1], ah[mt][0], ah[mt][1], ah[mt][2], ah[mt][3], bh1, bh3);
                }
            }
        }

        if (kt < NST - 1) {
            acc_G(WcS, fA, kb0 + (kt + 1) * KC, pd0, pd1);
            sts_A(bufn, fA, tid);
            CP_WAIT0();
        }
        __syncthreads();
    }

    // ---- G write: reduce pd over the 4 threads sharing a row ----
    pd0 += __shfl_xor_sync(0xffffffffu, pd0, 1);
    pd0 += __shfl_xor_sync(0xffffffffu, pd0, 2);
    pd1 += __shfl_xor_sync(0xffffffffu, pd1, 1);
    pd1 += __shfl_xor_sync(0xffffffffu, pd1, 2);
    if ((tid & 3) == 0) {
        const size_t gr = (size_t)(row0 + (tid >> 2)) * 2;
        g_G[gr]     = pd0;
        g_G[gr + 1] = pd1;
    }

    // ---- epilogue: register-paired V/U (permuted B), no Uact staging ----
    // ng in {0,1}: V cols;  ng+2: U cols for the SAME l, same (row,lane) map.
    // l = cw*32 + ng*16 + h*8 + (lane&3)*2 + (e&1)
    float* part = reinterpret_cast<float*>(smem);    // [4][128]

    float srow[2][2] = {{0.f, 0.f}, {0.f, 0.f}};     // [mt][rh]
#pragma unroll
    for (int ng = 0; ng < 2; ++ng)
#pragma unroll
        for (int h = 0; h < 2; ++h)
#pragma unroll
            for (int eo = 0; eo < 2; ++eo) {
                const int l = cw * 32 + ng * 16 + h * 8 + (lane & 3) * 2 + eo;
                const float bvl = __ldg(&bv[l]);
                const float bul = __ldg(&bu[l]);
                const float wwl = __ldg(&Ww[l]);
#pragma unroll
                for (int mt = 0; mt < 2; ++mt)
#pragma unroll
                    for (int rh = 0; rh < 2; ++rh) {
                        const int e = rh * 2 + eo;
                        float xv = acc[mt][ng][h][e]     + bvl;
                        float xu = acc[mt][ng + 2][h][e] + bul;
                        float su = 1.f / (1.f + __expf(-xu));
                        srow[mt][rh] += tanh_fast(xv) * wwl * su;
                    }
            }
#pragma unroll
    for (int mt = 0; mt < 2; ++mt)
#pragma unroll
        for (int rh = 0; rh < 2; ++rh) {
            srow[mt][rh] += __shfl_xor_sync(0xffffffffu, srow[mt][rh], 1);
            srow[mt][rh] += __shfl_xor_sync(0xffffffffu, srow[mt][rh], 2);
        }
    if ((lane & 3) == 0) {
#pragma unroll
        for (int mt = 0; mt < 2; ++mt)
#pragma unroll
            for (int rh = 0; rh < 2; ++rh) {
                int r = rw * 32 + mt * 16 + (lane >> 2) + rh * 8;
                part[cw * 128 + r] = srow[mt][rh];
            }
    }
    __syncthreads();

    if (tid < MT)
        A_pre[(size_t)(row0 + tid)] =
            part[tid] + part[128 + tid] + part[256 + tid] + part[384 + tid] + bw[0];
}

// ---------------------------------------------------------------------------
// Phase 2+3 merged: per-bag softmax -> A_sftmx, then
// out[b,k] = sum_t a[t]*G[b,t,k] + bc[k]*bias_rel
// ---------------------------------------------------------------------------
__global__ __launch_bounds__(256)
void mil_finish(const float* __restrict__ A_pre,
                const float* __restrict__ bc,
                float* __restrict__ Asm, float* __restrict__ out)
{
    __shared__ float sh0[256];
    __shared__ float sh1[256];
    __shared__ float sh2[256];
    const int b   = blockIdx.x;
    const int tid = threadIdx.x;
    const float* src = A_pre + (size_t)b * T_;

    const int t0 = tid, t1 = tid + 256;
    float v0 = src[t0];
    float v1 = (t1 < T_) ? src[t1] : -INFINITY;

    sh0[tid] = fmaxf(v0, v1);
    __syncthreads();
    for (int s = 128; s > 0; s >>= 1) {
        if (tid < s) sh0[tid] = fmaxf(sh0[tid], sh0[tid + s]);
        __syncthreads();
    }
    const float mx = sh0[0];
    __syncthreads();

    float e0 = expf(v0 - mx);
    float e1 = (t1 < T_) ? expf(v1 - mx) : 0.f;
    sh0[tid] = e0 + e1;
    __syncthreads();
    for (int s = 128; s > 0; s >>= 1) {
        if (tid < s) sh0[tid] += sh0[tid + s];
        __syncthreads();
    }
    const float inv = 1.f / sh0[0];
    __syncthreads();

    const float a0 = e0 * inv;
    const float a1 = e1 * inv;
    Asm[(size_t)b * T_ + t0] = a0;
    if (t1 < T_) Asm[(size_t)b * T_ + t1] = a1;

    const float* Gb = g_G + (size_t)b * T_ * 2;
    float c0 = a0 * Gb[t0 * 2]     + ((t1 < T_) ? a1 * Gb[t1 * 2]     : 0.f);
    float c1 = a0 * Gb[t0 * 2 + 1] + ((t1 < T_) ? a1 * Gb[t1 * 2 + 1] : 0.f);

    sh0[tid] = a0 + a1;   // bias_rel partial
    sh1[tid] = c0;
    sh2[tid] = c1;
    __syncthreads();
    for (int s = 128; s > 0; s >>= 1) {
        if (tid < s) {
            sh0[tid] += sh0[tid + s];
            sh1[tid] += sh1[tid + s];
            sh2[tid] += sh2[tid + s];
        }
        __syncthreads();
    }
    if (tid == 0) {
        const float bias_rel = sh0[0];
        out[(size_t)b * 2 + 0] = sh1[0] + bc[0] * bias_rel;
        out[(size_t)b * 2 + 1] = sh2[0] + bc[1] * bias_rel;
    }
}

// ---------------------------------------------------------------------------
// Launch: d_out = (out[256,2], A_sftmx[256,500], A_pre[256,1,500])
// ---------------------------------------------------------------------------
extern "C" void kernel_launch(void* const* d_in, const int* in_sizes, int n_in,
                              void* d_out, int out_size)
{
    const float* H  = (const float*)d_in[0];
    const float* Wv = (const float*)d_in[1];
    const float* bv = (const float*)d_in[2];
    const float* Wu = (const float*)d_in[3];
    const float* bu = (const float*)d_in[4];
    const float* Ww = (const float*)d_in[5];
    const float* bw = (const float*)d_in[6];
    const float* Wc = (const float*)d_in[7];
    const float* bc = (const float*)d_in[8];

    float* out   = (float*)d_out;               // [256,2]
    float* A_sm  = out + (size_t)B_ * 2;        // [256,500]
    float* A_pre = A_sm + (size_t)B_ * T_;      // [256,1,500]

    // one-time, non-stream host config (no-op during graph capture replays)
    static bool configured = false;
    if (!configured) {
        cudaFuncSetAttribute(mil_phase1_mma,
                             cudaFuncAttributeMaxDynamicSharedMemorySize, SMEM_P1);
        configured = true;
    }

    wsplit_kernel<<<(NN * M_) / 256, 256>>>(Wv, Wu);
    mil_phase1_mma<<<NROWS / MT, NTH, SMEM_P1>>>(H, bv, bu, Ww, bw, Wc, A_pre);
    mil_finish<<<B_, 256>>>(A_pre, bc, A_sm, out);
}

// round 15
// speedup vs baseline: 1.5473x; 1.0235x over previous
#include <cuda_runtime.h>
#include <cuda_fp16.h>
#include <stdint.h>
#include <math.h>

#define B_   256
#define T_   500
#define M_   512
#define L_   128
#define NROWS (B_ * T_)    // 128000

// ---- phase-1 tiling ----
#define MT   64             // rows / CTA  (grid 2000 -> tail ~3.5%)
#define NN   256            // cols, PERMUTED: group g owns {V[g*32..+32], U[g*32..+32]}
#define KC   64             // fp32 k per stage -> 128B fp16 rows (SW128)
#define NST  (M_ / KC)      // 8 stages
#define NTH  512            // 16 warps; warp tile 16x64; 2 CTAs/SM (thread cap)

// smem stage: {A 8K, B 32K} = 40KB; two stages + Wc 4K = 84KB
#define BUF     40960
#define SMEM_P1 (2 * BUF + 4096)   // 86016

// W (fp16), permuted rows (see wsplit), [n][k] row-major, 16B aligned
__device__ __align__(16) unsigned short g_Whi[NN * M_];
// fused per-row projection dots: G[b*T+t][k] = H[b,t,:]. Wc[k,:]
__device__ float g_G[NROWS * 2];

// ===================== helpers =====================
__device__ __forceinline__ uint32_t smem_u32(const void* p) {
    uint32_t a;
    asm("{ .reg .u64 t; cvta.to.shared.u64 t, %1; cvt.u32.u64 %0, t; }"
        : "=r"(a) : "l"(p));
    return a;
}
__device__ __forceinline__ uint32_t swz(uint32_t o) { return o ^ ((o >> 3) & 0x70); }

__device__ __forceinline__ void ldsm4(uint32_t a, uint32_t& r0, uint32_t& r1,
                                      uint32_t& r2, uint32_t& r3) {
    asm volatile("ldmatrix.sync.aligned.m8n8.x4.shared.b16 {%0,%1,%2,%3}, [%4];"
                 : "=r"(r0), "=r"(r1), "=r"(r2), "=r"(r3) : "r"(a));
}
__device__ __forceinline__ void mma16816(float* c, uint32_t a0, uint32_t a1,
                                         uint32_t a2, uint32_t a3,
                                         uint32_t b0, uint32_t b1) {
    asm volatile(
        "mma.sync.aligned.m16n8k16.row.col.f32.f16.f16.f32 "
        "{%0,%1,%2,%3}, {%4,%5,%6,%7}, {%8,%9}, {%0,%1,%2,%3};"
        : "+f"(c[0]), "+f"(c[1]), "+f"(c[2]), "+f"(c[3])
        : "r"(a0), "r"(a1), "r"(a2), "r"(a3), "r"(b0), "r"(b1));
}
#define CP16(dst, src) \
    asm volatile("cp.async.cg.shared.global [%0], [%1], 16;" :: "r"(dst), "l"(src))
#define CP_COMMIT() asm volatile("cp.async.commit_group;" ::: "memory")
#define CP_WAIT0()  asm volatile("cp.async.wait_group 0;" ::: "memory")
#define STS128(a, x, y, z, w) \
    asm volatile("st.shared.v4.b32 [%0], {%1,%2,%3,%4};" \
                 :: "r"(a), "r"(x), "r"(y), "r"(z), "r"(w))

__device__ __forceinline__ uint32_t h2_u32(float a, float b) {
    __half2 h = __floats2half2_rn(a, b);
    return *reinterpret_cast<uint32_t*>(&h);
}
__device__ __forceinline__ float tanh_fast(float x) {
    float y;
    asm("tanh.approx.f32 %0, %1;" : "=f"(y) : "f"(x));
    return y;
}

// ---------------------------------------------------------------------------
// Convert W to fp16 with PERMUTED row order (once per launch; 256KB).
// GEMM row n: g = n>>6, r = n&63; l = g*32 + (r&31);
//   r < 32  -> Wv[l];  r >= 32 -> Wu[l]  (register pairing in epilogue)
// ---------------------------------------------------------------------------
__global__ void wsplit_kernel(const float* __restrict__ Wv, const float* __restrict__ Wu)
{
    int idx = blockIdx.x * 256 + threadIdx.x;          // 0 .. 131071
    int n = idx >> 9, k = idx & 511;
    int g = n >> 6, r = n & 63;
    int l = g * 32 + (r & 31);
    float x = (r < 32) ? Wv[l * M_ + k] : Wu[l * M_ + k];
    __half h = __float2half_rn(x);
    g_Whi[idx] = *reinterpret_cast<unsigned short*>(&h);
}

// ---------------------------------------------------------------------------
// Phase 1: fp16 mma.sync GEMM (16x64 warp tiles, MT=64) + paired epilogue
//          + fused per-row Wc projection dots -> g_G
// ---------------------------------------------------------------------------
__device__ __forceinline__ void load_B_async(uint32_t bufb, int kt, int tid)
{
    const int row = tid >> 1, half = tid & 1;
    const unsigned short* sh = g_Whi + row * M_ + kt * KC + half * 32;
    const uint32_t dh = bufb + 8192;
#pragma unroll
    for (int j = 0; j < 4; ++j) {
        uint32_t off = swz((uint32_t)(row * 128 + (half * 4 + j) * 16));
        CP16(dh + off, sh + j * 8);
    }
}

// store A tile as fp16 (8 floats/thread -> 1 STS128)
__device__ __forceinline__ void sts_A(uint32_t bufb, const float4* f, int tid)
{
    const int row = tid >> 3, q = tid & 7;
    uint32_t w0 = h2_u32(f[0].x, f[0].y);
    uint32_t w1 = h2_u32(f[0].z, f[0].w);
    uint32_t w2 = h2_u32(f[1].x, f[1].y);
    uint32_t w3 = h2_u32(f[1].z, f[1].w);
    STS128(bufb + swz((uint32_t)(row * 128 + q * 16)), w0, w1, w2, w3);
}

// accumulate G partial dots from an fp32 A fragment (8 k values)
__device__ __forceinline__ void acc_G(const float* WcS, const float4* f, int kbase,
                                      float& pd0, float& pd1)
{
#pragma unroll
    for (int i = 0; i < 2; ++i) {
        float4 w0 = *reinterpret_cast<const float4*>(WcS + kbase + i * 4);
        float4 w1 = *reinterpret_cast<const float4*>(WcS + 512 + kbase + i * 4);
        pd0 += f[i].x * w0.x + f[i].y * w0.y + f[i].z * w0.z + f[i].w * w0.w;
        pd1 += f[i].x * w1.x + f[i].y * w1.y + f[i].z * w1.z + f[i].w * w1.w;
    }
}

__global__ __launch_bounds__(NTH, 2)
void mil_phase1_mma(const float* __restrict__ H,
                    const float* __restrict__ bv, const float* __restrict__ bu,
                    const float* __restrict__ Ww, const float* __restrict__ bw,
                    const float* __restrict__ Wc,
                    float* __restrict__ A_pre)
{
    extern __shared__ __align__(1024) char smem[];
    const uint32_t sb = smem_u32(smem);
    const int tid  = threadIdx.x;
    const int lane = tid & 31;
    const int warp = tid >> 5;
    const int rw   = warp >> 2;      // 0..3 row group (16 rows)
    const int cw   = warp & 3;       // 0..3 col group (64 permuted cols = 32 l)
    const int row0 = blockIdx.x * MT;

    float* WcS = reinterpret_cast<float*>(smem + 2 * BUF);   // [2][512]
    WcS[tid]       = Wc[tid];
    WcS[tid + 512] = Wc[tid + 512];

    float acc[4][2][4];              // [ng][h][e]
#pragma unroll
    for (int b = 0; b < 4; ++b)
#pragma unroll
        for (int c = 0; c < 2; ++c)
#pragma unroll
            for (int d = 0; d < 4; ++d) acc[b][c][d] = 0.f;

    const float* gA = H + (size_t)(row0 + (tid >> 3)) * M_ + (tid & 7) * 8;
    const int kb0 = (tid & 7) * 8;        // k base of this thread's fragment
    float pd0 = 0.f, pd1 = 0.f;           // G partial dots

    // ldmatrix per-lane address components
    const int lrow = lane & 15;
    const int lko  = (lane >> 4) * 16;
    const int arow = (rw * 16 + lrow) * 128;

    // ---- prologue: stage 0 ----
    load_B_async(sb, 0, tid);
    CP_COMMIT();
    float4 f0[2];
    f0[0] = *reinterpret_cast<const float4*>(gA);
    f0[1] = *reinterpret_cast<const float4*>(gA + 4);
    sts_A(sb, f0, tid);
    CP_WAIT0();
    __syncthreads();            // also publishes WcS
    acc_G(WcS, f0, kb0, pd0, pd1);

    // ---- main loop ----
    for (int kt = 0; kt < NST; ++kt) {
        const uint32_t bufc = sb + (uint32_t)(kt & 1) * BUF;
        const uint32_t bufn = sb + (uint32_t)((kt + 1) & 1) * BUF;

        float4 fA[2];
        if (kt < NST - 1) {
            const float* s = gA + (kt + 1) * KC;
            fA[0] = *reinterpret_cast<const float4*>(s);
            fA[1] = *reinterpret_cast<const float4*>(s + 4);
            load_B_async(bufn, kt + 1, tid);
            CP_COMMIT();
        }

        // compute stage kt: 4 k16-steps, 8 HMMA each
#pragma unroll
        for (int ks = 0; ks < 4; ++ks) {
            const uint32_t kb = (uint32_t)(ks * 32 + lko);
            uint32_t a0, a1, a2, a3;
            ldsm4(bufc + swz((uint32_t)arow + kb), a0, a1, a2, a3);
#pragma unroll
            for (int ng = 0; ng < 4; ++ng) {
                const uint32_t bro = (uint32_t)((cw * 64 + ng * 16 + lrow) * 128) + kb;
                uint32_t bh0, bh1, bh2, bh3;
                ldsm4(bufc + 8192 + swz(bro), bh0, bh1, bh2, bh3);
                mma16816(acc[ng][0], a0, a1, a2, a3, bh0, bh2);
                mma16816(acc[ng][1], a0, a1, a2, a3, bh1, bh3);
            }
        }

        if (kt < NST - 1) {
            acc_G(WcS, fA, kb0 + (kt + 1) * KC, pd0, pd1);
            sts_A(bufn, fA, tid);
            CP_WAIT0();
        }
        __syncthreads();
    }

    // ---- G write: reduce pd over the 8 threads sharing a row ----
    pd0 += __shfl_xor_sync(0xffffffffu, pd0, 1);
    pd0 += __shfl_xor_sync(0xffffffffu, pd0, 2);
    pd0 += __shfl_xor_sync(0xffffffffu, pd0, 4);
    pd1 += __shfl_xor_sync(0xffffffffu, pd1, 1);
    pd1 += __shfl_xor_sync(0xffffffffu, pd1, 2);
    pd1 += __shfl_xor_sync(0xffffffffu, pd1, 4);
    if ((tid & 7) == 0) {
        const size_t gr = (size_t)(row0 + (tid >> 3)) * 2;
        g_G[gr]     = pd0;
        g_G[gr + 1] = pd1;
    }

    // ---- epilogue: register-paired V/U (permuted B) ----
    // ng in {0,1}: V cols; ng+2: U cols for the SAME l, same (row,lane) map.
    // l = cw*32 + ng*16 + h*8 + (lane&3)*2 + eo
    float* part = reinterpret_cast<float*>(smem);    // [4][64]

    float srow[2] = {0.f, 0.f};                      // [rh]
#pragma unroll
    for (int ng = 0; ng < 2; ++ng)
#pragma unroll
        for (int h = 0; h < 2; ++h)
#pragma unroll
            for (int eo = 0; eo < 2; ++eo) {
                const int l = cw * 32 + ng * 16 + h * 8 + (lane & 3) * 2 + eo;
                const float bvl = __ldg(&bv[l]);
                const float bul = __ldg(&bu[l]);
                const float wwl = __ldg(&Ww[l]);
#pragma unroll
                for (int rh = 0; rh < 2; ++rh) {
                    const int e = rh * 2 + eo;
                    float xv = acc[ng][h][e]     + bvl;
                    float xu = acc[ng + 2][h][e] + bul;
                    float su = 1.f / (1.f + __expf(-xu));
                    srow[rh] += tanh_fast(xv) * wwl * su;
                }
            }
#pragma unroll
    for (int rh = 0; rh < 2; ++rh) {
        srow[rh] += __shfl_xor_sync(0xffffffffu, srow[rh], 1);
        srow[rh] += __shfl_xor_sync(0xffffffffu, srow[rh], 2);
    }
    if ((lane & 3) == 0) {
#pragma unroll
        for (int rh = 0; rh < 2; ++rh) {
            int r = rw * 16 + (lane >> 2) + rh * 8;
            part[cw * 64 + r] = srow[rh];
        }
    }
    __syncthreads();

    if (tid < MT)
        A_pre[(size_t)(row0 + tid)] =
            part[tid] + part[64 + tid] + part[128 + tid] + part[192 + tid] + bw[0];
}

// ---------------------------------------------------------------------------
// Phase 2+3 merged: per-bag softmax -> A_sftmx, then
// out[b,k] = sum_t a[t]*G[b,t,k] + bc[k]*bias_rel
// ---------------------------------------------------------------------------
__global__ __launch_bounds__(256)
void mil_finish(const float* __restrict__ A_pre,
                const float* __restrict__ bc,
                float* __restrict__ Asm, float* __restrict__ out)
{
    __shared__ float sh0[256];
    __shared__ float sh1[256];
    __shared__ float sh2[256];
    const int b   = blockIdx.x;
    const int tid = threadIdx.x;
    const float* src = A_pre + (size_t)b * T_;

    const int t0 = tid, t1 = tid + 256;
    float v0 = src[t0];
    float v1 = (t1 < T_) ? src[t1] : -INFINITY;

    sh0[tid] = fmaxf(v0, v1);
    __syncthreads();
    for (int s = 128; s > 0; s >>= 1) {
        if (tid < s) sh0[tid] = fmaxf(sh0[tid], sh0[tid + s]);
        __syncthreads();
    }
    const float mx = sh0[0];
    __syncthreads();

    float e0 = expf(v0 - mx);
    float e1 = (t1 < T_) ? expf(v1 - mx) : 0.f;
    sh0[tid] = e0 + e1;
    __syncthreads();
    for (int s = 128; s > 0; s >>= 1) {
        if (tid < s) sh0[tid] += sh0[tid + s];
        __syncthreads();
    }
    const float inv = 1.f / sh0[0];
    __syncthreads();

    const float a0 = e0 * inv;
    const float a1 = e1 * inv;
    Asm[(size_t)b * T_ + t0] = a0;
    if (t1 < T_) Asm[(size_t)b * T_ + t1] = a1;

    const float* Gb = g_G + (size_t)b * T_ * 2;
    float c0 = a0 * Gb[t0 * 2]     + ((t1 < T_) ? a1 * Gb[t1 * 2]     : 0.f);
    float c1 = a0 * Gb[t0 * 2 + 1] + ((t1 < T_) ? a1 * Gb[t1 * 2 + 1] : 0.f);

    sh0[tid] = a0 + a1;   // bias_rel partial
    sh1[tid] = c0;
    sh2[tid] = c1;
    __syncthreads();
    for (int s = 128; s > 0; s >>= 1) {
        if (tid < s) {
            sh0[tid] += sh0[tid + s];
            sh1[tid] += sh1[tid + s];
            sh2[tid] += sh2[tid + s];
        }
        __syncthreads();
    }
    if (tid == 0) {
        const float bias_rel = sh0[0];
        out[(size_t)b * 2 + 0] = sh1[0] + bc[0] * bias_rel;
        out[(size_t)b * 2 + 1] = sh2[0] + bc[1] * bias_rel;
    }
}

// ---------------------------------------------------------------------------
// Launch: d_out = (out[256,2], A_sftmx[256,500], A_pre[256,1,500])
// ---------------------------------------------------------------------------
extern "C" void kernel_launch(void* const* d_in, const int* in_sizes, int n_in,
                              void* d_out, int out_size)
{
    const float* H  = (const float*)d_in[0];
    const float* Wv = (const float*)d_in[1];
    const float* bv = (const float*)d_in[2];
    const float* Wu = (const float*)d_in[3];
    const float* bu = (const float*)d_in[4];
    const float* Ww = (const float*)d_in[5];
    const float* bw = (const float*)d_in[6];
    const float* Wc = (const float*)d_in[7];
    const float* bc = (const float*)d_in[8];

    float* out   = (float*)d_out;               // [256,2]
    float* A_sm  = out + (size_t)B_ * 2;        // [256,500]
    float* A_pre = A_sm + (size_t)B_ * T_;      // [256,1,500]

    // one-time, non-stream host config (no-op during graph capture replays)
    static bool configured = false;
    if (!configured) {
        cudaFuncSetAttribute(mil_phase1_mma,
                             cudaFuncAttributeMaxDynamicSharedMemorySize, SMEM_P1);
        configured = true;
    }

    wsplit_kernel<<<(NN * M_) / 256, 256>>>(Wv, Wu);
    mil_phase1_mma<<<NROWS / MT, NTH, SMEM_P1>>>(H, bv, bu, Ww, bw, Wc, A_pre);
    mil_finish<<<B_, 256>>>(A_pre, bc, A_sm, out);
}